// round 2
// baseline (speedup 1.0000x reference)
#include <cuda_runtime.h>
#include <cuda_bf16.h>
#include <cstdint>

#define B_SZ   2048
#define L_SZ   200000
#define H_SZ   64

#define BM 128
#define BN 128
#define TM 8
#define TN 8
#define KP (H_SZ / 2)        // 32 k-pairs
#define NTHREADS 256
#define GX ((L_SZ + BN - 1) / BN)   // 1563
#define NY (B_SZ / BM)              // 16
#define SSTRIDE 66                  // smem row stride in floats (pad 2)

__device__ float g_partial[(size_t)GX * B_SZ];   // [bx][m] layout for coalesced rowsum
__device__ float g_rowsum[B_SZ];

__device__ __forceinline__ unsigned long long ffma2(unsigned long long a,
                                                    unsigned long long b,
                                                    unsigned long long c) {
    unsigned long long d;
    asm("fma.rn.f32x2 %0, %1, %2, %3;" : "=l"(d) : "l"(a), "l"(b), "l"(c));
    return d;
}

// ---------------------------------------------------------------------------
// Kernel 1: gather return_embed into output tail (odd float offset -> scalar).
// ---------------------------------------------------------------------------
__global__ void prep_kernel(const int* __restrict__ label,
                            const float* __restrict__ table,
                            float* __restrict__ out_embed) {
    int i = blockIdx.x * blockDim.x + threadIdx.x;
    if (i < B_SZ) {
        int lab = label[i];
        const float* src = table + (size_t)lab * H_SZ;
        float* dst = out_embed + (size_t)i * H_SZ;
        #pragma unroll
        for (int k = 0; k < H_SZ; k++) dst[k] = src[k];
    }
}

// ---------------------------------------------------------------------------
// Kernel 2: 128x128 register-tiled GEMM with f32x2 packed FMA.
// Each block owns one 128-column strip, loops over all 16 m-tiles.
// Thread (tx,ty): tx=tid&15 covers n = nblk + j*16 + tx (j=0..7),
//                 ty=tid>>4 covers m = mblk + ty*8 + i (i=0..7).
// Accumulators packed over k-pairs (lo=even k, hi=odd k).
// ---------------------------------------------------------------------------
extern __shared__ float s_mem[];

__global__ __launch_bounds__(NTHREADS, 1)
void logits_kernel(const int* __restrict__ label,
                   const float* __restrict__ table,
                   const float* __restrict__ W,
                   const float* __restrict__ b,
                   float* __restrict__ out) {
    float* w_s = s_mem;                       // [BN][SSTRIDE]
    float* e_s = s_mem + BN * SSTRIDE;        // [BM][SSTRIDE]

    const int tid = threadIdx.x;
    const int tx  = tid & 15;
    const int ty  = tid >> 4;
    const int bx  = blockIdx.x;
    const int nblk = bx * BN;

    // ---- Load W tile (once per block) : rows nblk..nblk+127 ----
    // 128 rows x 32 float2 = 4096 float2, 16 per thread.
    for (int idx = tid; idx < BN * (H_SZ / 2); idx += NTHREADS) {
        int r  = idx >> 5;          // local n
        int k2 = idx & 31;          // float2 index within row
        int n  = nblk + r;
        float2 v = make_float2(0.f, 0.f);
        if (n < L_SZ)
            v = *reinterpret_cast<const float2*>(W + (size_t)n * H_SZ + k2 * 2);
        *reinterpret_cast<float2*>(&w_s[r * SSTRIDE + k2 * 2]) = v;
    }

    // ---- Bias for this thread's 8 columns (loop-invariant) ----
    float bj[TN];
    bool  vj[TN];
    #pragma unroll
    for (int j = 0; j < TN; j++) {
        int n = nblk + j * 16 + tx;
        vj[j] = (n < L_SZ);
        bj[j] = vj[j] ? __ldg(&b[n]) : 0.0f;
    }

    for (int y = 0; y < NY; y++) {
        const int mblk = y * BM;
        __syncthreads();   // protect e_s from previous iteration's readers

        // ---- Gather embed tile: e_s[m][:] = table[label[mblk+m]][:] ----
        for (int idx = tid; idx < BM * (H_SZ / 2); idx += NTHREADS) {
            int m  = idx >> 5;
            int k2 = idx & 31;
            int lab = __ldg(&label[mblk + m]);
            float2 v = *reinterpret_cast<const float2*>(
                table + (size_t)lab * H_SZ + k2 * 2);
            *reinterpret_cast<float2*>(&e_s[m * SSTRIDE + k2 * 2]) = v;
        }
        __syncthreads();

        // ---- Main FFMA2 loop ----
        unsigned long long acc[TM][TN];
        #pragma unroll
        for (int i = 0; i < TM; i++)
            #pragma unroll
            for (int j = 0; j < TN; j++) acc[i][j] = 0ull;

        #pragma unroll 2
        for (int kp = 0; kp < KP; kp++) {
            unsigned long long ev[TM];
            #pragma unroll
            for (int i = 0; i < TM; i++)
                ev[i] = *reinterpret_cast<const unsigned long long*>(
                    &e_s[(ty * TM + i) * SSTRIDE + kp * 2]);
            #pragma unroll
            for (int j = 0; j < TN; j++) {
                unsigned long long wv =
                    *reinterpret_cast<const unsigned long long*>(
                        &w_s[(j * 16 + tx) * SSTRIDE + kp * 2]);
                #pragma unroll
                for (int i = 0; i < TM; i++)
                    acc[i][j] = ffma2(ev[i], wv, acc[i][j]);
            }
        }

        // ---- Epilogue: sigmoid, store, exp row-partials ----
        #pragma unroll
        for (int i = 0; i < TM; i++) {
            const int m = mblk + ty * TM + i;
            float exsum = 0.0f;
            #pragma unroll
            for (int j = 0; j < TN; j++) {
                float lo = __uint_as_float((unsigned)(acc[i][j] & 0xffffffffull));
                float hi = __uint_as_float((unsigned)(acc[i][j] >> 32));
                float v  = lo + hi + bj[j];
                float sig = __fdividef(1.0f, 1.0f + __expf(-v));
                if (vj[j]) {
                    out[(size_t)m * L_SZ + nblk + j * 16 + tx] = sig;
                    exsum += __expf(sig);
                }
            }
            // reduce over 16 tx lanes (fixed order, deterministic)
            #pragma unroll
            for (int off = 8; off > 0; off >>= 1)
                exsum += __shfl_down_sync(0xffffffffu, exsum, off, 16);
            if (tx == 0)
                g_partial[(size_t)bx * B_SZ + m] = exsum;
        }
    }
}

// ---------------------------------------------------------------------------
// Kernel 3: deterministic row-sum over the GX block partials (coalesced).
// ---------------------------------------------------------------------------
__global__ void rowsum_kernel() {
    int m = blockIdx.x * blockDim.x + threadIdx.x;
    if (m < B_SZ) {
        float s = 0.0f;
        for (int j = 0; j < GX; j++) s += g_partial[(size_t)j * B_SZ + m];
        g_rowsum[m] = s;
    }
}

// ---------------------------------------------------------------------------
// Kernel 4: loss = mean(log(rowsum_i) - logits[i, label[i]]).
// ---------------------------------------------------------------------------
__global__ void loss_kernel(const int* __restrict__ label,
                            const float* __restrict__ logits,
                            float* __restrict__ out_loss) {
    __shared__ float red[256];
    float s = 0.0f;
    for (int i = threadIdx.x; i < B_SZ; i += 256) {
        float lg = logits[(size_t)i * L_SZ + label[i]];
        s += logf(g_rowsum[i]) - lg;
    }
    red[threadIdx.x] = s;
    __syncthreads();
    for (int off = 128; off > 0; off >>= 1) {
        if (threadIdx.x < off) red[threadIdx.x] += red[threadIdx.x + off];
        __syncthreads();
    }
    if (threadIdx.x == 0) out_loss[0] = red[0] / (float)B_SZ;
}

// ---------------------------------------------------------------------------
extern "C" void kernel_launch(void* const* d_in, const int* in_sizes, int n_in,
                              void* d_out, int out_size) {
    const int*   label = (const int*)d_in[0];
    const float* table = (const float*)d_in[1];
    const float* W     = (const float*)d_in[2];
    const float* b     = (const float*)d_in[3];
    float* out = (float*)d_out;

    float* out_logits = out;
    float* out_loss   = out + (size_t)B_SZ * L_SZ;
    float* out_embed  = out + (size_t)B_SZ * L_SZ + 1;

    const int smem_bytes = (BM + BN) * SSTRIDE * sizeof(float);   // 67584
    cudaFuncSetAttribute(logits_kernel,
                         cudaFuncAttributeMaxDynamicSharedMemorySize, smem_bytes);

    prep_kernel<<<(B_SZ + 255) / 256, 256>>>(label, table, out_embed);
    logits_kernel<<<GX, NTHREADS, smem_bytes>>>(label, table, W, b, out_logits);
    rowsum_kernel<<<(B_SZ + 255) / 256, 256>>>();
    loss_kernel<<<1, 256>>>(label, out_logits, out_loss);
}

// round 5
// speedup vs baseline: 3.2434x; 3.2434x over previous
#include <cuda_runtime.h>
#include <cuda_bf16.h>
#include <cstdint>

#define B_SZ   2048
#define L_SZ   200000
#define H_SZ   64

#define BM 128
#define BN 128
#define NTHREADS 256
#define GX ((L_SZ + BN - 1) / BN)   // 1563
#define NY (B_SZ / BM)              // 16

#define SWZ128(off) ((off) ^ (((off) >> 3) & 0x70))

__device__ float g_partial[(size_t)GX * B_SZ];
__device__ float g_rowsum[B_SZ];
__device__ float g_terms[B_SZ];

// ---------------------------------------------------------------------------
__device__ __forceinline__ uint32_t smem_u32(const void* p) {
    uint32_t a;
    asm("{ .reg .u64 t; cvta.to.shared.u64 t, %1; cvt.u32.u64 %0, t; }"
        : "=r"(a) : "l"(p));
    return a;
}

__device__ __forceinline__ void ldm_x4(uint32_t& r0, uint32_t& r1,
                                       uint32_t& r2, uint32_t& r3, uint32_t addr) {
    asm volatile("ldmatrix.sync.aligned.m8n8.x4.shared.b16 {%0,%1,%2,%3}, [%4];"
                 : "=r"(r0), "=r"(r1), "=r"(r2), "=r"(r3) : "r"(addr));
}
// NON-transposed: W[n][k] rows directly provide the B fragment (k-pairs per lane).
__device__ __forceinline__ void ldm_x2(uint32_t& r0, uint32_t& r1, uint32_t addr) {
    asm volatile("ldmatrix.sync.aligned.m8n8.x2.shared.b16 {%0,%1}, [%2];"
                 : "=r"(r0), "=r"(r1) : "r"(addr));
}
__device__ __forceinline__ void mma_bf16(float* d, const uint32_t* a, const uint32_t* bfr) {
    asm volatile(
        "mma.sync.aligned.m16n8k16.row.col.f32.bf16.bf16.f32 "
        "{%0,%1,%2,%3}, {%4,%5,%6,%7}, {%8,%9}, {%0,%1,%2,%3};"
        : "+f"(d[0]), "+f"(d[1]), "+f"(d[2]), "+f"(d[3])
        : "r"(a[0]), "r"(a[1]), "r"(a[2]), "r"(a[3]), "r"(bfr[0]), "r"(bfr[1]));
}

// exp(s) for s in (0,1): degree-6 Taylor (abs err < 3e-4, ~1e-6 near 0.5)
__device__ __forceinline__ float exp01(float s) {
    float p = 1.388888889e-3f;
    p = fmaf(p, s, 8.333333333e-3f);
    p = fmaf(p, s, 4.166666667e-2f);
    p = fmaf(p, s, 1.666666667e-1f);
    p = fmaf(p, s, 0.5f);
    p = fmaf(p, s, 1.0f);
    p = fmaf(p, s, 1.0f);
    return p;
}

// Convert+store one 16B chunk (8 fp32 -> 8 bf16) into a swizzled 128B-row tile.
__device__ __forceinline__ void cvt_store_chunk(char* tile, int row, int ch,
                                                const float4* src_row) {
    float4 v0 = __ldg(src_row + ch * 2);
    float4 v1 = __ldg(src_row + ch * 2 + 1);
    uint4 u;
    __nv_bfloat162 t;
    t = __float22bfloat162_rn(make_float2(v0.x, v0.y)); u.x = *(uint32_t*)&t;
    t = __float22bfloat162_rn(make_float2(v0.z, v0.w)); u.y = *(uint32_t*)&t;
    t = __float22bfloat162_rn(make_float2(v1.x, v1.y)); u.z = *(uint32_t*)&t;
    t = __float22bfloat162_rn(make_float2(v1.z, v1.w)); u.w = *(uint32_t*)&t;
    uint32_t off = row * 128 + ch * 16;
    *reinterpret_cast<uint4*>(tile + SWZ128(off)) = u;
}

// ---------------------------------------------------------------------------
// Kernel 1: gather return_embed into output tail (odd float offset -> scalar).
// ---------------------------------------------------------------------------
__global__ void prep_kernel(const int* __restrict__ label,
                            const float* __restrict__ table,
                            float* __restrict__ out_embed) {
    int i = blockIdx.x * blockDim.x + threadIdx.x;
    if (i < B_SZ) {
        int lab = label[i];
        const float* src = table + (size_t)lab * H_SZ;
        float* dst = out_embed + (size_t)i * H_SZ;
        #pragma unroll
        for (int k = 0; k < H_SZ; k++) dst[k] = src[k];
    }
}

// ---------------------------------------------------------------------------
// Kernel 2: bf16 mma.sync GEMM + sigmoid epilogue + exp row-partials.
// One CTA per 128-column strip (W tile resident in smem), loops 16 m-tiles.
// Warp w: rows (w&1)*64..+63, cols (w>>1)*32..+31 of the 128x128 tile.
// ---------------------------------------------------------------------------
__global__ __launch_bounds__(NTHREADS, 2)
void logits_kernel(const int* __restrict__ label,
                   const float* __restrict__ table,
                   const float* __restrict__ W,
                   const float* __restrict__ b,
                   float* __restrict__ out) {
    __shared__ __align__(1024) char w_s[BN * 128];   // bf16 [n][64], swizzled
    __shared__ __align__(1024) char a_s[BM * 128];   // bf16 [m][64], swizzled
    __shared__ float bia_s[BN];
    __shared__ float red_s[BM][4];

    const int tid  = threadIdx.x;
    const int wid  = tid >> 5;
    const int lane = tid & 31;
    const int bx   = blockIdx.x;
    const int nblk = bx * BN;

    const uint32_t a_base = smem_u32(a_s);
    const uint32_t w_base = smem_u32(w_s);

    const int wm = (wid & 1) * 64;        // warp row offset in tile
    const int wn = (wid >> 1) * 32;       // warp col offset in tile

    // ---- Load W tile (bf16, swizzled) + bias; zero-fill rows beyond L_SZ ----
    for (int idx = tid; idx < BN * 8; idx += NTHREADS) {
        int r = idx >> 3, ch = idx & 7;
        int n = nblk + r;
        if (n < L_SZ) {
            cvt_store_chunk(w_s, r, ch,
                            reinterpret_cast<const float4*>(W + (size_t)n * H_SZ));
        } else {
            uint32_t off = r * 128 + ch * 16;
            *reinterpret_cast<uint4*>(w_s + SWZ128(off)) = make_uint4(0, 0, 0, 0);
        }
    }
    for (int idx = tid; idx < BN; idx += NTHREADS) {
        int n = nblk + idx;
        bia_s[idx] = (n < L_SZ) ? __ldg(&b[n]) : 0.0f;
    }

    for (int y = 0; y < NY; y++) {
        const int mblk = y * BM;

        // ---- Gather A tile: a_s[m][:] = bf16(table[label[mblk+m]][:]) ----
        for (int idx = tid; idx < BM * 8; idx += NTHREADS) {
            int r = idx >> 3, ch = idx & 7;
            int lab = __ldg(&label[mblk + r]);
            cvt_store_chunk(a_s, r, ch,
                            reinterpret_cast<const float4*>(table + (size_t)lab * H_SZ));
        }
        __syncthreads();

        // ---- MMA mainloop: 4 k-steps of 16 ----
        float acc[4][4][4];
        #pragma unroll
        for (int i = 0; i < 4; i++)
            #pragma unroll
            for (int j = 0; j < 4; j++)
                #pragma unroll
                for (int e = 0; e < 4; e++) acc[i][j][e] = 0.0f;

        #pragma unroll
        for (int ks = 0; ks < 4; ks++) {
            uint32_t a[4][4];
            #pragma unroll
            for (int i = 0; i < 4; i++) {
                uint32_t off = (uint32_t)(wm + i * 16 + (lane & 15)) * 128
                             + ks * 32 + (lane >> 4) * 16;
                ldm_x4(a[i][0], a[i][1], a[i][2], a[i][3], a_base + SWZ128(off));
            }
            uint32_t bf[4][2];
            #pragma unroll
            for (int j = 0; j < 4; j++) {
                uint32_t off = (uint32_t)(wn + j * 8 + (lane & 7)) * 128
                             + ks * 32 + ((lane >> 3) & 1) * 16;
                ldm_x2(bf[j][0], bf[j][1], w_base + SWZ128(off));
            }
            #pragma unroll
            for (int i = 0; i < 4; i++)
                #pragma unroll
                for (int j = 0; j < 4; j++)
                    mma_bf16(acc[i][j], a[i], bf[j]);
        }

        // ---- Epilogue: sigmoid, store pairs, exp row-partials ----
        float ex0[4], ex1[4];
        #pragma unroll
        for (int i = 0; i < 4; i++) { ex0[i] = 0.0f; ex1[i] = 0.0f; }

        #pragma unroll
        for (int i = 0; i < 4; i++) {
            const int r0 = wm + i * 16 + (lane >> 2);
            const int r1 = r0 + 8;
            #pragma unroll
            for (int j = 0; j < 4; j++) {
                const int col = wn + j * 8 + (lane & 3) * 2;
                const int gn  = nblk + col;
                const float bb0 = bia_s[col];
                const float bb1 = bia_s[col + 1];
                float s00 = __fdividef(1.0f, 1.0f + __expf(-(acc[i][j][0] + bb0)));
                float s01 = __fdividef(1.0f, 1.0f + __expf(-(acc[i][j][1] + bb1)));
                float s10 = __fdividef(1.0f, 1.0f + __expf(-(acc[i][j][2] + bb0)));
                float s11 = __fdividef(1.0f, 1.0f + __expf(-(acc[i][j][3] + bb1)));
                if (gn < L_SZ) {
                    *reinterpret_cast<float2*>(&out[(size_t)(mblk + r0) * L_SZ + gn])
                        = make_float2(s00, s01);
                    *reinterpret_cast<float2*>(&out[(size_t)(mblk + r1) * L_SZ + gn])
                        = make_float2(s10, s11);
                    ex0[i] += exp01(s00) + exp01(s01);
                    ex1[i] += exp01(s10) + exp01(s11);
                }
            }
        }
        // quad-lane reduction (lanes r*4..r*4+3), fixed order
        #pragma unroll
        for (int i = 0; i < 4; i++) {
            float v0 = ex0[i], v1 = ex1[i];
            v0 += __shfl_down_sync(0xffffffffu, v0, 2, 4);
            v0 += __shfl_down_sync(0xffffffffu, v0, 1, 4);
            v1 += __shfl_down_sync(0xffffffffu, v1, 2, 4);
            v1 += __shfl_down_sync(0xffffffffu, v1, 1, 4);
            if ((lane & 3) == 0) {
                red_s[wm + i * 16 + (lane >> 2)][wid >> 1]     = v0;
                red_s[wm + i * 16 + (lane >> 2) + 8][wid >> 1] = v1;
            }
        }
        __syncthreads();

        if (tid < BM) {
            float s = red_s[tid][0] + red_s[tid][1] + red_s[tid][2] + red_s[tid][3];
            g_partial[(size_t)bx * B_SZ + mblk + tid] = s;
        }
        __syncthreads();   // red_s / a_s reuse next iteration
    }
}

// ---------------------------------------------------------------------------
// Kernel 3: deterministic row-sum over the GX block partials (coalesced).
// ---------------------------------------------------------------------------
__global__ void rowsum_kernel() {
    int m = blockIdx.x * blockDim.x + threadIdx.x;
    if (m < B_SZ) {
        float s = 0.0f;
        for (int j = 0; j < GX; j++) s += g_partial[(size_t)j * B_SZ + m];
        g_rowsum[m] = s;
    }
}

// ---------------------------------------------------------------------------
// Kernel 4a/4b: loss terms + final fixed-order reduction.
// ---------------------------------------------------------------------------
__global__ void loss_terms_kernel(const int* __restrict__ label,
                                  const float* __restrict__ logits) {
    int i = blockIdx.x * blockDim.x + threadIdx.x;
    if (i < B_SZ)
        g_terms[i] = logf(g_rowsum[i]) - logits[(size_t)i * L_SZ + label[i]];
}

__global__ void loss_reduce_kernel(float* __restrict__ out_loss) {
    __shared__ float red[1024];
    int t = threadIdx.x;
    red[t] = g_terms[t] + g_terms[t + 1024];
    __syncthreads();
    for (int off = 512; off > 0; off >>= 1) {
        if (t < off) red[t] += red[t + off];
        __syncthreads();
    }
    if (t == 0) out_loss[0] = red[0] / (float)B_SZ;
}

// ---------------------------------------------------------------------------
extern "C" void kernel_launch(void* const* d_in, const int* in_sizes, int n_in,
                              void* d_out, int out_size) {
    const int*   label = (const int*)d_in[0];
    const float* table = (const float*)d_in[1];
    const float* W     = (const float*)d_in[2];
    const float* b     = (const float*)d_in[3];
    float* out = (float*)d_out;

    float* out_logits = out;
    float* out_loss   = out + (size_t)B_SZ * L_SZ;
    float* out_embed  = out + (size_t)B_SZ * L_SZ + 1;

    prep_kernel<<<(B_SZ + 255) / 256, 256>>>(label, table, out_embed);
    logits_kernel<<<GX, NTHREADS>>>(label, table, W, b, out_logits);
    rowsum_kernel<<<(B_SZ + 255) / 256, 256>>>();
    loss_terms_kernel<<<(B_SZ + 255) / 256, 256>>>(label, out_logits);
    loss_reduce_kernel<<<1, 1024>>>(out_loss);
}

// round 6
// speedup vs baseline: 4.4035x; 1.3577x over previous
#include <cuda_runtime.h>
#include <cuda_bf16.h>
#include <cstdint>

#define B_SZ   2048
#define L_SZ   200000
#define H_SZ   64

#define BM 128
#define BN 128
#define NTHREADS 256
#define GX ((L_SZ + BN - 1) / BN)   // 1563
#define NY (B_SZ / BM)              // 16

#define SWZ128(off) ((off) ^ (((off) >> 3) & 0x70))

__device__ float g_partial[(size_t)GX * B_SZ];
__device__ float g_terms[B_SZ];

// ---------------------------------------------------------------------------
__device__ __forceinline__ uint32_t smem_u32(const void* p) {
    uint32_t a;
    asm("{ .reg .u64 t; cvta.to.shared.u64 t, %1; cvt.u32.u64 %0, t; }"
        : "=r"(a) : "l"(p));
    return a;
}
__device__ __forceinline__ void ldm_x4(uint32_t& r0, uint32_t& r1,
                                       uint32_t& r2, uint32_t& r3, uint32_t addr) {
    asm volatile("ldmatrix.sync.aligned.m8n8.x4.shared.b16 {%0,%1,%2,%3}, [%4];"
                 : "=r"(r0), "=r"(r1), "=r"(r2), "=r"(r3) : "r"(addr));
}
__device__ __forceinline__ void ldm_x2(uint32_t& r0, uint32_t& r1, uint32_t addr) {
    asm volatile("ldmatrix.sync.aligned.m8n8.x2.shared.b16 {%0,%1}, [%2];"
                 : "=r"(r0), "=r"(r1) : "r"(addr));
}
__device__ __forceinline__ void mma_bf16(float* d, const uint32_t* a, const uint32_t* bfr) {
    asm volatile(
        "mma.sync.aligned.m16n8k16.row.col.f32.bf16.bf16.f32 "
        "{%0,%1,%2,%3}, {%4,%5,%6,%7}, {%8,%9}, {%0,%1,%2,%3};"
        : "+f"(d[0]), "+f"(d[1]), "+f"(d[2]), "+f"(d[3])
        : "r"(a[0]), "r"(a[1]), "r"(a[2]), "r"(a[3]), "r"(bfr[0]), "r"(bfr[1]));
}
// sigmoid via HW tanh: 1 MUFU + 2 FMA
__device__ __forceinline__ float fast_sigmoid(float v) {
    float t;
    asm("tanh.approx.f32 %0, %1;" : "=f"(t) : "f"(v * 0.5f));
    return fmaf(0.5f, t, 0.5f);
}
// exp(s) for s in (0,1): degree-6 Taylor
__device__ __forceinline__ float exp01(float s) {
    float p = 1.388888889e-3f;
    p = fmaf(p, s, 8.333333333e-3f);
    p = fmaf(p, s, 4.166666667e-2f);
    p = fmaf(p, s, 1.666666667e-1f);
    p = fmaf(p, s, 0.5f);
    p = fmaf(p, s, 1.0f);
    p = fmaf(p, s, 1.0f);
    return p;
}
__device__ __forceinline__ uint4 pack_bf16(float4 v0, float4 v1) {
    uint4 u;
    __nv_bfloat162 t;
    t = __float22bfloat162_rn(make_float2(v0.x, v0.y)); u.x = *(uint32_t*)&t;
    t = __float22bfloat162_rn(make_float2(v0.z, v0.w)); u.y = *(uint32_t*)&t;
    t = __float22bfloat162_rn(make_float2(v1.x, v1.y)); u.z = *(uint32_t*)&t;
    t = __float22bfloat162_rn(make_float2(v1.z, v1.w)); u.w = *(uint32_t*)&t;
    return u;
}

// ---------------------------------------------------------------------------
// Kernel 1: gather return_embed into output tail.
// ---------------------------------------------------------------------------
__global__ void prep_kernel(const int* __restrict__ label,
                            const float* __restrict__ table,
                            float* __restrict__ out_embed) {
    int i = blockIdx.x * blockDim.x + threadIdx.x;
    if (i < B_SZ) {
        int lab = label[i];
        const float* src = table + (size_t)lab * H_SZ;
        float* dst = out_embed + (size_t)i * H_SZ;
        #pragma unroll
        for (int k = 0; k < H_SZ; k++) dst[k] = src[k];
    }
}

// ---------------------------------------------------------------------------
// Kernel 2: bf16 mma.sync GEMM + sigmoid epilogue, software-pipelined gather.
// ---------------------------------------------------------------------------
__global__ __launch_bounds__(NTHREADS, 2)
void logits_kernel(const int* __restrict__ label,
                   const float* __restrict__ table,
                   const float* __restrict__ W,
                   const float* __restrict__ b,
                   float* __restrict__ out) {
    __shared__ __align__(1024) char w_s[BN * 128];       // bf16 [n][64], swizzled
    __shared__ __align__(1024) char a_s[2][BM * 128];    // double-buffered A tile
    __shared__ float bia_s[BN];
    __shared__ float red_s[2][BM][4];

    const int tid  = threadIdx.x;
    const int wid  = tid >> 5;
    const int lane = tid & 31;
    const int bx   = blockIdx.x;
    const int nblk = bx * BN;

    const uint32_t w_base = smem_u32(w_s);

    const int wm = (wid & 1) * 64;
    const int wn = (wid >> 1) * 32;

    // Per-thread gather assignment (4 chunks per tile)
    int g_row[4], g_ch[4];
    #pragma unroll
    for (int i = 0; i < 4; i++) {
        int idx = tid + i * NTHREADS;
        g_row[i] = idx >> 3;
        g_ch[i]  = idx & 7;
    }

    // ---- W tile + bias ----
    for (int idx = tid; idx < BN * 8; idx += NTHREADS) {
        int r = idx >> 3, ch = idx & 7;
        int n = nblk + r;
        uint32_t off = r * 128 + ch * 16;
        if (n < L_SZ) {
            const float4* src = reinterpret_cast<const float4*>(W + (size_t)n * H_SZ);
            *reinterpret_cast<uint4*>(w_s + SWZ128(off)) =
                pack_bf16(__ldg(src + ch * 2), __ldg(src + ch * 2 + 1));
        } else {
            *reinterpret_cast<uint4*>(w_s + SWZ128(off)) = make_uint4(0, 0, 0, 0);
        }
    }
    for (int idx = tid; idx < BN; idx += NTHREADS) {
        int n = nblk + idx;
        bia_s[idx] = (n < L_SZ) ? __ldg(&b[n]) : 0.0f;
    }

    // ---- Prologue: gather tile 0 into a_s[0] ----
    #pragma unroll
    for (int i = 0; i < 4; i++) {
        int lab = __ldg(&label[g_row[i]]);
        const float4* src = reinterpret_cast<const float4*>(table + (size_t)lab * H_SZ);
        uint32_t off = g_row[i] * 128 + g_ch[i] * 16;
        *reinterpret_cast<uint4*>(a_s[0] + SWZ128(off)) =
            pack_bf16(__ldg(src + g_ch[i] * 2), __ldg(src + g_ch[i] * 2 + 1));
    }
    __syncthreads();

    for (int y = 0; y < NY; y++) {
        const int mblk = y * BM;
        const int buf = y & 1;
        const uint32_t a_base = smem_u32(a_s[buf]);

        // ---- Issue next tile's gather LDGs early (latency hidden by MMA) ----
        float4 pf0[4], pf1[4];
        const bool has_next = (y + 1 < NY);
        if (has_next) {
            #pragma unroll
            for (int i = 0; i < 4; i++) {
                int lab = __ldg(&label[mblk + BM + g_row[i]]);
                const float4* src = reinterpret_cast<const float4*>(table + (size_t)lab * H_SZ);
                pf0[i] = __ldg(src + g_ch[i] * 2);
                pf1[i] = __ldg(src + g_ch[i] * 2 + 1);
            }
        }

        // ---- MMA mainloop: 4 k-steps of 16 ----
        float acc[4][4][4];
        #pragma unroll
        for (int i = 0; i < 4; i++)
            #pragma unroll
            for (int j = 0; j < 4; j++)
                #pragma unroll
                for (int e = 0; e < 4; e++) acc[i][j][e] = 0.0f;

        #pragma unroll
        for (int ks = 0; ks < 4; ks++) {
            uint32_t a[4][4];
            #pragma unroll
            for (int i = 0; i < 4; i++) {
                uint32_t off = (uint32_t)(wm + i * 16 + (lane & 15)) * 128
                             + ks * 32 + (lane >> 4) * 16;
                ldm_x4(a[i][0], a[i][1], a[i][2], a[i][3], a_base + SWZ128(off));
            }
            uint32_t bf[4][2];
            #pragma unroll
            for (int j = 0; j < 4; j++) {
                uint32_t off = (uint32_t)(wn + j * 8 + (lane & 7)) * 128
                             + ks * 32 + ((lane >> 3) & 1) * 16;
                ldm_x2(bf[j][0], bf[j][1], w_base + SWZ128(off));
            }
            #pragma unroll
            for (int i = 0; i < 4; i++)
                #pragma unroll
                for (int j = 0; j < 4; j++)
                    mma_bf16(acc[i][j], a[i], bf[j]);
        }

        // ---- Epilogue: sigmoid (tanh), store, exp row-partials ----
        float ex0[4], ex1[4];
        #pragma unroll
        for (int i = 0; i < 4; i++) { ex0[i] = 0.0f; ex1[i] = 0.0f; }

        #pragma unroll
        for (int i = 0; i < 4; i++) {
            const int r0 = wm + i * 16 + (lane >> 2);
            const int r1 = r0 + 8;
            #pragma unroll
            for (int j = 0; j < 4; j++) {
                const int col = wn + j * 8 + (lane & 3) * 2;
                const int gn  = nblk + col;
                const float bb0 = bia_s[col];
                const float bb1 = bia_s[col + 1];
                float s00 = fast_sigmoid(acc[i][j][0] + bb0);
                float s01 = fast_sigmoid(acc[i][j][1] + bb1);
                float s10 = fast_sigmoid(acc[i][j][2] + bb0);
                float s11 = fast_sigmoid(acc[i][j][3] + bb1);
                if (gn < L_SZ) {
                    *reinterpret_cast<float2*>(&out[(size_t)(mblk + r0) * L_SZ + gn])
                        = make_float2(s00, s01);
                    *reinterpret_cast<float2*>(&out[(size_t)(mblk + r1) * L_SZ + gn])
                        = make_float2(s10, s11);
                    ex0[i] += exp01(s00) + exp01(s01);
                    ex1[i] += exp01(s10) + exp01(s11);
                }
            }
        }
        #pragma unroll
        for (int i = 0; i < 4; i++) {
            float v0 = ex0[i], v1 = ex1[i];
            v0 += __shfl_down_sync(0xffffffffu, v0, 2, 4);
            v0 += __shfl_down_sync(0xffffffffu, v0, 1, 4);
            v1 += __shfl_down_sync(0xffffffffu, v1, 2, 4);
            v1 += __shfl_down_sync(0xffffffffu, v1, 1, 4);
            if ((lane & 3) == 0) {
                red_s[buf][wm + i * 16 + (lane >> 2)][wid >> 1]     = v0;
                red_s[buf][wm + i * 16 + (lane >> 2) + 8][wid >> 1] = v1;
            }
        }

        // ---- Commit prefetched A tile to the other buffer ----
        if (has_next) {
            #pragma unroll
            for (int i = 0; i < 4; i++) {
                uint32_t off = g_row[i] * 128 + g_ch[i] * 16;
                *reinterpret_cast<uint4*>(a_s[buf ^ 1] + SWZ128(off)) =
                    pack_bf16(pf0[i], pf1[i]);
            }
        }
        __syncthreads();

        if (tid < BM) {
            float s = red_s[buf][tid][0] + red_s[buf][tid][1]
                    + red_s[buf][tid][2] + red_s[buf][tid][3];
            g_partial[(size_t)bx * B_SZ + mblk + tid] = s;
        }
        // no second sync: next iteration writes red_s[buf^1] / a_s[buf] is done
    }
}

// ---------------------------------------------------------------------------
// Kernel 3: fused deterministic row-sum + loss terms.
// ---------------------------------------------------------------------------
__global__ void rowsum_terms_kernel(const int* __restrict__ label,
                                    const float* __restrict__ logits) {
    int m = blockIdx.x * blockDim.x + threadIdx.x;
    if (m < B_SZ) {
        float s = 0.0f;
        for (int j = 0; j < GX; j++) s += g_partial[(size_t)j * B_SZ + m];
        g_terms[m] = logf(s) - logits[(size_t)m * L_SZ + label[m]];
    }
}

__global__ void loss_reduce_kernel(float* __restrict__ out_loss) {
    __shared__ float red[1024];
    int t = threadIdx.x;
    red[t] = g_terms[t] + g_terms[t + 1024];
    __syncthreads();
    for (int off = 512; off > 0; off >>= 1) {
        if (t < off) red[t] += red[t + off];
        __syncthreads();
    }
    if (t == 0) out_loss[0] = red[0] / (float)B_SZ;
}

// ---------------------------------------------------------------------------
extern "C" void kernel_launch(void* const* d_in, const int* in_sizes, int n_in,
                              void* d_out, int out_size) {
    const int*   label = (const int*)d_in[0];
    const float* table = (const float*)d_in[1];
    const float* W     = (const float*)d_in[2];
    const float* b     = (const float*)d_in[3];
    float* out = (float*)d_out;

    float* out_logits = out;
    float* out_loss   = out + (size_t)B_SZ * L_SZ;
    float* out_embed  = out + (size_t)B_SZ * L_SZ + 1;

    prep_kernel<<<(B_SZ + 255) / 256, 256>>>(label, table, out_embed);
    logits_kernel<<<GX, NTHREADS>>>(label, table, W, b, out_logits);
    rowsum_terms_kernel<<<(B_SZ + 255) / 256, 256>>>(label, out_logits);
    loss_reduce_kernel<<<1, 1024>>>(out_loss);
}